// round 4
// baseline (speedup 1.0000x reference)
#include <cuda_runtime.h>
#include <cuda_bf16.h>

// Scratch: inverse L2 norms per row (N = 100000). Static device array per the
// no-allocation rule. Sized with headroom.
#define MAX_N 131072
__device__ float g_inv[MAX_N];

// Kernel 1: one warp per row computes 1 / max(||row||, 1e-12).
__global__ void norm_kernel(const float* __restrict__ emb, int N) {
    int warps_per_block = blockDim.x >> 5;
    int row = blockIdx.x * warps_per_block + (threadIdx.x >> 5);
    if (row >= N) return;
    int lane = threadIdx.x & 31;
    const float4* r = reinterpret_cast<const float4*>(emb) + (size_t)row * 32;
    float4 v = r[lane];
    float ss = v.x * v.x + v.y * v.y + v.z * v.z + v.w * v.w;
    #pragma unroll
    for (int o = 16; o > 0; o >>= 1)
        ss += __shfl_xor_sync(0xffffffffu, ss, o);
    if (lane == 0)
        g_inv[row] = 1.0f / fmaxf(sqrtf(ss), 1e-12f);
}

// Kernel 2: persistent warps, 4 edges per warp per iteration, 8 lanes per
// edge. dvec (4 float4) and scale are loaded ONCE per warp lifetime; the loop
// body issues only the 8 independent row gathers + 2 index loads.
// Indices are int32 (JAX x64 disabled).
__global__ void __launch_bounds__(256) edge_kernel(
        const float* __restrict__ emb,
        const int* __restrict__ src,
        const int* __restrict__ dst,
        const float* __restrict__ dvec,
        const float* __restrict__ scale,
        float* __restrict__ out,
        int E) {
    int lane = threadIdx.x & 31;
    int g    = lane >> 3;    // edge group within warp: 0..3
    int l8   = lane & 7;     // lane within group

    int warp_global = blockIdx.x * (blockDim.x >> 5) + (threadIdx.x >> 5);
    int nwarps      = gridDim.x * (blockDim.x >> 5);

    // Hoisted invariants: lane's slice of d, and the scalar scale.
    const float4* dv4 = reinterpret_cast<const float4*>(dvec);
    float4 d0 = __ldg(&dv4[l8]);
    float4 d1 = __ldg(&dv4[l8 + 8]);
    float4 d2 = __ldg(&dv4[l8 + 16]);
    float4 d3 = __ldg(&dv4[l8 + 24]);
    float  sc = __ldg(scale);

    for (int base = warp_global * 4; base < E; base += nwarps * 4) {
        int e = base + g;
        bool valid = (e < E);
        int ee = valid ? e : 0;

        int s = __ldg(&src[ee]);
        int t = __ldg(&dst[ee]);

        const float4* rs = reinterpret_cast<const float4*>(emb) + (size_t)s * 32;
        const float4* rt = reinterpret_cast<const float4*>(emb) + (size_t)t * 32;

        // 8 independent LDG.128 per lane.
        float4 a0 = __ldg(&rs[l8]);
        float4 a1 = __ldg(&rs[l8 + 8]);
        float4 a2 = __ldg(&rs[l8 + 16]);
        float4 a3 = __ldg(&rs[l8 + 24]);
        float4 b0 = __ldg(&rt[l8]);
        float4 b1 = __ldg(&rt[l8 + 8]);
        float4 b2 = __ldg(&rt[l8 + 16]);
        float4 b3 = __ldg(&rt[l8 + 24]);

        float p = 0.0f;
        p += a0.x * d0.x * b0.x; p += a0.y * d0.y * b0.y;
        p += a0.z * d0.z * b0.z; p += a0.w * d0.w * b0.w;
        p += a1.x * d1.x * b1.x; p += a1.y * d1.y * b1.y;
        p += a1.z * d1.z * b1.z; p += a1.w * d1.w * b1.w;
        p += a2.x * d2.x * b2.x; p += a2.y * d2.y * b2.y;
        p += a2.z * d2.z * b2.z; p += a2.w * d2.w * b2.w;
        p += a3.x * d3.x * b3.x; p += a3.y * d3.y * b3.y;
        p += a3.z * d3.z * b3.z; p += a3.w * d3.w * b3.w;

        // Reduce across the 8-lane group.
        p += __shfl_xor_sync(0xffffffffu, p, 4);
        p += __shfl_xor_sync(0xffffffffu, p, 2);
        p += __shfl_xor_sync(0xffffffffu, p, 1);

        if (l8 == 0 && valid) {
            float f = g_inv[s] * g_inv[t] * sc;
            out[e] = p * f;   // lanes 0,8,16,24 -> 4 consecutive floats
        }
    }
}

extern "C" void kernel_launch(void* const* d_in, const int* in_sizes, int n_in,
                              void* d_out, int out_size) {
    const float* emb   = (const float*)d_in[0];
    const int*   src   = (const int*)d_in[1];
    const int*   dst   = (const int*)d_in[2];
    const float* dvec  = (const float*)d_in[3];
    const float* scale = (const float*)d_in[4];
    float* out = (float*)d_out;

    int N = in_sizes[0] / 128;   // H = 128
    int E = in_sizes[1];

    const int TPB = 256;                 // 8 warps per block
    int warps_per_block = TPB / 32;

    int norm_blocks = (N + warps_per_block - 1) / warps_per_block;
    norm_kernel<<<norm_blocks, TPB>>>(emb, N);

    // Persistent-ish grid: ~16 blocks per SM, each warp loops ~8 iterations.
    int edge_blocks = 148 * 16;
    int max_blocks = (E + warps_per_block * 4 - 1) / (warps_per_block * 4);
    if (edge_blocks > max_blocks) edge_blocks = max_blocks;
    edge_kernel<<<edge_blocks, TPB>>>(emb, src, dst, dvec, scale, out, E);
}

// round 5
// speedup vs baseline: 1.0446x; 1.0446x over previous
#include <cuda_runtime.h>
#include <cuda_bf16.h>

// Scratch: inverse L2 norms per row (N = 100000). Static device array per the
// no-allocation rule. Sized with headroom.
#define MAX_N 131072
__device__ float g_inv[MAX_N];

// Kernel 1: one warp per row computes 1 / max(||row||, 1e-12).
__global__ void norm_kernel(const float* __restrict__ emb, int N) {
    int warps_per_block = blockDim.x >> 5;
    int row = blockIdx.x * warps_per_block + (threadIdx.x >> 5);
    if (row >= N) return;
    int lane = threadIdx.x & 31;
    const float4* r = reinterpret_cast<const float4*>(emb) + (size_t)row * 32;
    float4 v = r[lane];
    float ss = v.x * v.x + v.y * v.y + v.z * v.z + v.w * v.w;
    #pragma unroll
    for (int o = 16; o > 0; o >>= 1)
        ss += __shfl_xor_sync(0xffffffffu, ss, o);
    if (lane == 0)
        g_inv[row] = 1.0f / fmaxf(sqrtf(ss), 1e-12f);
}

// Kernel 2: persistent warps, 4 edges per warp per iteration, 8 lanes/edge.
// Software-pipelined: next iteration's indices are prefetched before the
// current gathers are consumed; g_inv products are issued right after the
// indices arrive so they overlap the row gathers. d lives in shared memory
// (broadcast reads) to cut register pressure and raise occupancy.
__global__ void __launch_bounds__(256) edge_kernel(
        const float* __restrict__ emb,
        const int* __restrict__ src,
        const int* __restrict__ dst,
        const float* __restrict__ dvec,
        const float* __restrict__ scale,
        float* __restrict__ out,
        int E) {
    __shared__ float4 sd[32];
    if (threadIdx.x < 32)
        sd[threadIdx.x] = reinterpret_cast<const float4*>(dvec)[threadIdx.x];
    __syncthreads();

    int lane = threadIdx.x & 31;
    int g    = lane >> 3;    // edge group within warp: 0..3
    int l8   = lane & 7;     // lane within group

    int warp_global = blockIdx.x * (blockDim.x >> 5) + (threadIdx.x >> 5);
    int nwarps      = gridDim.x * (blockDim.x >> 5);
    int stride      = nwarps * 4;

    float sc = __ldg(scale);

    int base = warp_global * 4;
    if (base >= E) return;

    // Prologue: indices for the first iteration.
    int e0 = base + g;
    int ee = (e0 < E) ? e0 : 0;
    int s = __ldg(&src[ee]);
    int t = __ldg(&dst[ee]);

    for (; base < E; base += stride) {
        int e = base + g;
        bool valid = (e < E);

        // Prefetch next iteration's indices (off the critical path).
        int nb = base + stride;
        int sn = 0, tn = 0;
        if (nb < E) {
            int en = (nb + g < E) ? nb + g : 0;
            sn = __ldg(&src[en]);
            tn = __ldg(&dst[en]);
        }

        // Issue the norm-product loads early so they overlap the row gathers.
        float fi = 0.0f;
        if (l8 == 0)
            fi = g_inv[s] * g_inv[t] * sc;

        const float4* rs = reinterpret_cast<const float4*>(emb) + (size_t)s * 32;
        const float4* rt = reinterpret_cast<const float4*>(emb) + (size_t)t * 32;

        // 8 independent LDG.128 per lane.
        float4 a0 = __ldg(&rs[l8]);
        float4 a1 = __ldg(&rs[l8 + 8]);
        float4 a2 = __ldg(&rs[l8 + 16]);
        float4 a3 = __ldg(&rs[l8 + 24]);
        float4 b0 = __ldg(&rt[l8]);
        float4 b1 = __ldg(&rt[l8 + 8]);
        float4 b2 = __ldg(&rt[l8 + 16]);
        float4 b3 = __ldg(&rt[l8 + 24]);

        float4 d0 = sd[l8];
        float4 d1 = sd[l8 + 8];
        float4 d2 = sd[l8 + 16];
        float4 d3 = sd[l8 + 24];

        float p = 0.0f;
        p += a0.x * d0.x * b0.x; p += a0.y * d0.y * b0.y;
        p += a0.z * d0.z * b0.z; p += a0.w * d0.w * b0.w;
        p += a1.x * d1.x * b1.x; p += a1.y * d1.y * b1.y;
        p += a1.z * d1.z * b1.z; p += a1.w * d1.w * b1.w;
        p += a2.x * d2.x * b2.x; p += a2.y * d2.y * b2.y;
        p += a2.z * d2.z * b2.z; p += a2.w * d2.w * b2.w;
        p += a3.x * d3.x * b3.x; p += a3.y * d3.y * b3.y;
        p += a3.z * d3.z * b3.z; p += a3.w * d3.w * b3.w;

        // Reduce across the 8-lane group.
        p += __shfl_xor_sync(0xffffffffu, p, 4);
        p += __shfl_xor_sync(0xffffffffu, p, 2);
        p += __shfl_xor_sync(0xffffffffu, p, 1);

        if (l8 == 0 && valid)
            out[e] = p * fi;   // lanes 0,8,16,24 -> 4 consecutive floats

        s = sn;
        t = tn;
    }
}

extern "C" void kernel_launch(void* const* d_in, const int* in_sizes, int n_in,
                              void* d_out, int out_size) {
    const float* emb   = (const float*)d_in[0];
    const int*   src   = (const int*)d_in[1];
    const int*   dst   = (const int*)d_in[2];
    const float* dvec  = (const float*)d_in[3];
    const float* scale = (const float*)d_in[4];
    float* out = (float*)d_out;

    int N = in_sizes[0] / 128;   // H = 128
    int E = in_sizes[1];

    const int TPB = 256;                 // 8 warps per block
    int warps_per_block = TPB / 32;

    int norm_blocks = (N + warps_per_block - 1) / warps_per_block;
    norm_kernel<<<norm_blocks, TPB>>>(emb, N);

    // ~16 blocks/SM launched; grid-stride loop -> ~8 iterations per warp.
    int edge_blocks = 148 * 16;
    int max_blocks = (E + warps_per_block * 4 - 1) / (warps_per_block * 4);
    if (edge_blocks > max_blocks) edge_blocks = max_blocks;
    edge_kernel<<<edge_blocks, TPB>>>(emb, src, dst, dvec, scale, out, E);
}

// round 7
// speedup vs baseline: 1.3701x; 1.3117x over previous
#include <cuda_runtime.h>
#include <cuda_fp16.h>
#include <cuda_bf16.h>

// fp16 cache of L2-normalized embedding rows. N = 100000, H = 128.
// 131072 * 128 halves = 33.5 MB static device array (no allocation).
#define MAX_N 131072
__device__ uint2 g_en16[MAX_N * 32];   // row*32 + lane -> 4 halves (8 B)

// Kernel A: one warp per row. Computes inv = 1/max(||row||, 1e-12) and writes
// the normalized row as fp16 (natural element order, 2 B per element).
__global__ void norm16_kernel(const float* __restrict__ emb, int N) {
    int row = blockIdx.x * (blockDim.x >> 5) + (threadIdx.x >> 5);
    if (row >= N) return;
    int lane = threadIdx.x & 31;
    const float4* r = reinterpret_cast<const float4*>(emb) + (size_t)row * 32;
    float4 v = r[lane];
    float ss = v.x * v.x + v.y * v.y + v.z * v.z + v.w * v.w;
    #pragma unroll
    for (int o = 16; o > 0; o >>= 1)
        ss += __shfl_xor_sync(0xffffffffu, ss, o);
    float inv = 1.0f / fmaxf(sqrtf(ss), 1e-12f);

    __half2 h0 = __float22half2_rn(make_float2(v.x * inv, v.y * inv));
    __half2 h1 = __float22half2_rn(make_float2(v.z * inv, v.w * inv));
    uint2 packed;
    packed.x = *reinterpret_cast<unsigned int*>(&h0);
    packed.y = *reinterpret_cast<unsigned int*>(&h1);
    g_en16[(size_t)row * 32 + lane] = packed;
}

// dot over 8 halves (one uint4 from each row) with fp32 d pairs.
__device__ __forceinline__ float dot8(uint4 a, uint4 b, const float2* __restrict__ dp) {
    const __half2* pa = reinterpret_cast<const __half2*>(&a);
    const __half2* pb = reinterpret_cast<const __half2*>(&b);
    float acc = 0.0f;
    #pragma unroll
    for (int k = 0; k < 4; k++) {
        float2 fa = __half22float2(pa[k]);
        float2 fb = __half22float2(pb[k]);
        float2 dd = dp[k];
        acc += fa.x * dd.x * fb.x;
        acc += fa.y * dd.y * fb.y;
    }
    return acc;
}

// Kernel B: persistent warps, 8 edges per warp per iteration. Two 4-edge
// sets (A and B); 8 lanes per edge; each lane issues 8 independent full-line
// LDG.128 gathers (2 per row, 4 rows). Rows are pre-normalized fp16, so no
// per-edge norm lookups. Indices are int32 (JAX x64 disabled).
__global__ void __launch_bounds__(256) edge_kernel(
        const int* __restrict__ src,
        const int* __restrict__ dst,
        const float* __restrict__ dvec,
        const float* __restrict__ scale,
        float* __restrict__ out,
        int E) {
    __shared__ float2 sd2[64];           // d as fp32 pairs
    if (threadIdx.x < 64)
        sd2[threadIdx.x] = reinterpret_cast<const float2*>(dvec)[threadIdx.x];
    __syncthreads();

    int lane = threadIdx.x & 31;
    int g    = lane >> 3;                // edge group: 0..3
    int l8   = lane & 7;                 // lane within group

    int warp_global = blockIdx.x * (blockDim.x >> 5) + (threadIdx.x >> 5);
    int nwarps      = gridDim.x * (blockDim.x >> 5);
    int stride      = nwarps * 8;

    float sc = __ldg(scale);
    const uint4* en = reinterpret_cast<const uint4*>(g_en16);

    int base = warp_global * 8;
    if (base >= E) return;

    // Prologue: indices for first iteration (clamped; stores are guarded).
    int eA = base + g, eB = base + 4 + g;
    int sA = __ldg(&src[min(eA, E - 1)]);
    int tA = __ldg(&dst[min(eA, E - 1)]);
    int sB = __ldg(&src[min(eB, E - 1)]);
    int tB = __ldg(&dst[min(eB, E - 1)]);

    for (; base < E; base += stride) {
        eA = base + g;
        eB = base + 4 + g;

        // Prefetch next iteration's indices off the critical path.
        int nb = base + stride;
        int sAn = 0, tAn = 0, sBn = 0, tBn = 0;
        if (nb < E) {
            int neA = min(nb + g, E - 1);
            int neB = min(nb + 4 + g, E - 1);
            sAn = __ldg(&src[neA]);
            tAn = __ldg(&dst[neA]);
            sBn = __ldg(&src[neB]);
            tBn = __ldg(&dst[neB]);
        }

        const uint4* rsA = en + (size_t)sA * 16;
        const uint4* rtA = en + (size_t)tA * 16;
        const uint4* rsB = en + (size_t)sB * 16;
        const uint4* rtB = en + (size_t)tB * 16;

        // 8 independent LDG.128; each row is 2 full 128 B lines.
        uint4 a0 = __ldg(&rsA[l8]);
        uint4 a1 = __ldg(&rsA[l8 + 8]);
        uint4 b0 = __ldg(&rtA[l8]);
        uint4 b1 = __ldg(&rtA[l8 + 8]);
        uint4 c0 = __ldg(&rsB[l8]);
        uint4 c1 = __ldg(&rsB[l8 + 8]);
        uint4 f0 = __ldg(&rtB[l8]);
        uint4 f1 = __ldg(&rtB[l8 + 8]);

        const float2* dp0 = sd2 + 4 * l8;        // halves 8*l8 .. 8*l8+7
        const float2* dp1 = sd2 + 32 + 4 * l8;   // halves 64+8*l8 ..

        float pA = dot8(a0, b0, dp0) + dot8(a1, b1, dp1);
        float pB = dot8(c0, f0, dp0) + dot8(c1, f1, dp1);

        // Reduce each across the 8-lane group.
        #pragma unroll
        for (int o = 4; o > 0; o >>= 1) {
            pA += __shfl_xor_sync(0xffffffffu, pA, o);
            pB += __shfl_xor_sync(0xffffffffu, pB, o);
        }

        if (l8 == 0) {
            if (eA < E) out[eA] = pA * sc;   // lanes 0,8,16,24 -> coalesced
            if (eB < E) out[eB] = pB * sc;
        }

        sA = sAn; tA = tAn; sB = sBn; tB = tBn;
    }
}

extern "C" void kernel_launch(void* const* d_in, const int* in_sizes, int n_in,
                              void* d_out, int out_size) {
    const float* emb   = (const float*)d_in[0];
    const int*   src   = (const int*)d_in[1];
    const int*   dst   = (const int*)d_in[2];
    const float* dvec  = (const float*)d_in[3];
    const float* scale = (const float*)d_in[4];
    float* out = (float*)d_out;

    int N = in_sizes[0] / 128;   // H = 128
    int E = in_sizes[1];

    const int TPB = 256;
    int warps_per_block = TPB / 32;

    int norm_blocks = (N + warps_per_block - 1) / warps_per_block;
    norm16_kernel<<<norm_blocks, TPB>>>(emb, N);

    // Persistent-ish grid; each warp strides over 8-edge chunks.
    int edge_blocks = 148 * 8;
    int max_blocks = (E + warps_per_block * 8 - 1) / (warps_per_block * 8);
    if (edge_blocks > max_blocks) edge_blocks = max_blocks;
    edge_kernel<<<edge_blocks, TPB>>>(src, dst, dvec, scale, out, E);
}